// round 15
// baseline (speedup 1.0000x reference)
#include <cuda_runtime.h>
#include <cuda_bf16.h>
#include <cstdint>

#define N_NODES 200000
#define N_EDGES 800000
#define D 128
#define NT 1563            // ceil(200000/128); last tile has 64 valid rows
#define GRID_MLP 148
#define SCAN_BLKS 196      // ceil(200000/1024)

// ---------------------------------------------------------------------------
// Device scratch (allocation-free rule).
// ---------------------------------------------------------------------------
__device__ float g_agg[(size_t)N_NODES * D];
// CSR for edge->receiver gather
__device__ int g_hist[N_NODES];
__device__ int g_off[N_NODES + 1];
__device__ int g_cur[N_NODES];
__device__ int g_elist[N_EDGES];
__device__ int g_bsum[256];
__device__ int g_boff[256];
// Fragment-major weights: uint4 = {hi_b0, hi_b1, lo_b0, lo_b1} per (nb, ks, lane)
__device__ uint4 g_W1f[16 * 16 * 32];   // [nb][ksg 0..15][lane]
__device__ uint4 g_W2f[16 * 8 * 32];    // [nb][ksg 0..7][lane]

// ---------------------------------------------------------------------------
// helpers
// ---------------------------------------------------------------------------
__device__ __forceinline__ uint32_t smem_u32(const void* p) {
    uint32_t a;
    asm("{ .reg .u64 t; cvta.to.shared.u64 t, %1; cvt.u32.u64 %0, t; }"
        : "=r"(a) : "l"(p));
    return a;
}
__device__ __forceinline__ uint32_t pack_bf16x2(float lo, float hi) {
    uint32_t r;
    asm("cvt.rn.bf16x2.f32 %0, %1, %2;" : "=r"(r) : "f"(hi), "f"(lo));
    return r;
}
__device__ __forceinline__ void split2(float v0, float v1,
                                       uint32_t& hp, uint32_t& lp) {
    hp = pack_bf16x2(v0, v1);
    float h0 = __uint_as_float(hp << 16);
    float h1 = __uint_as_float(hp & 0xffff0000u);
    lp = pack_bf16x2(v0 - h0, v1 - h1);
}
__device__ __forceinline__ void ldsm_x4(uint32_t (&r)[4], uint32_t addr) {
    asm volatile("ldmatrix.sync.aligned.m8n8.x4.shared.b16 {%0,%1,%2,%3}, [%4];"
                 : "=r"(r[0]), "=r"(r[1]), "=r"(r[2]), "=r"(r[3]) : "r"(addr));
}
__device__ __forceinline__ void mma_bf16(float (&d)[4], const uint32_t (&a)[4],
                                         uint32_t b0, uint32_t b1) {
    asm volatile(
        "mma.sync.aligned.m16n8k16.row.col.f32.bf16.bf16.f32 "
        "{%0,%1,%2,%3}, {%4,%5,%6,%7}, {%8,%9}, {%0,%1,%2,%3};"
        : "+f"(d[0]), "+f"(d[1]), "+f"(d[2]), "+f"(d[3])
        : "r"(a[0]), "r"(a[1]), "r"(a[2]), "r"(a[3]), "r"(b0), "r"(b1));
}
__device__ __forceinline__ void cp_async16(uint32_t dst, const void* src) {
    asm volatile("cp.async.ca.shared.global [%0], [%1], 16;"
                 :: "r"(dst), "l"(src) : "memory");
}
#define CP_COMMIT() asm volatile("cp.async.commit_group;" ::: "memory")
#define CP_WAIT0()  asm volatile("cp.async.wait_group 0;" ::: "memory")
#define BAR1()   asm volatile("bar.sync 1, 256;" ::: "memory")
#define BARALL() asm volatile("bar.sync 2, 320;" ::: "memory")

// ---------------------------------------------------------------------------
// Kernel 0: fragment-major hi/lo bf16 weights.
// ---------------------------------------------------------------------------
__global__ void prep_w_kernel(const float* __restrict__ W1,
                              const float* __restrict__ W2) {
    int i = blockIdx.x * blockDim.x + threadIdx.x;
    if (i < 8192) {                       // W1: 16 nb x 16 ks x 32 lanes
        int lane = i & 31, ks = (i >> 5) & 15, nb = i >> 9;
        int n = nb * 8 + (lane >> 2);
        int k0 = ks * 16 + 2 * (lane & 3);
        float v00 = W1[(k0 + 0) * 128 + n], v01 = W1[(k0 + 1) * 128 + n];
        float v10 = W1[(k0 + 8) * 128 + n], v11 = W1[(k0 + 9) * 128 + n];
        uint32_t hb0, lb0, hb1, lb1;
        split2(v00, v01, hb0, lb0);
        split2(v10, v11, hb1, lb1);
        g_W1f[i] = make_uint4(hb0, hb1, lb0, lb1);
    }
    if (i < 4096) {                       // W2: 16 nb x 8 ks x 32 lanes
        int lane = i & 31, ks = (i >> 5) & 7, nb = i >> 8;
        int n = nb * 8 + (lane >> 2);
        int k0 = ks * 16 + 2 * (lane & 3);
        float v00 = W2[(k0 + 0) * 128 + n], v01 = W2[(k0 + 1) * 128 + n];
        float v10 = W2[(k0 + 8) * 128 + n], v11 = W2[(k0 + 9) * 128 + n];
        uint32_t hb0, lb0, hb1, lb1;
        split2(v00, v01, hb0, lb0);
        split2(v10, v11, hb1, lb1);
        g_W2f[i] = make_uint4(hb0, hb1, lb0, lb1);
    }
}

// ---------------------------------------------------------------------------
// CSR build: zero hist -> histogram -> scan -> fill.
// ---------------------------------------------------------------------------
__global__ void zero_hist_kernel() {
    int i = blockIdx.x * 1024 + threadIdx.x;
    if (i < N_NODES) g_hist[i] = 0;
}
__global__ void hist_kernel(const int* __restrict__ recv) {
    int e = blockIdx.x * blockDim.x + threadIdx.x;
    if (e < N_EDGES) atomicAdd(&g_hist[recv[e]], 1);
}
__global__ void scan1_kernel() {
    __shared__ int s[1024];
    int t = threadIdx.x;
    int i = blockIdx.x * 1024 + t;
    int v = (i < N_NODES) ? g_hist[i] : 0;
    s[t] = v;
    __syncthreads();
    #pragma unroll
    for (int d = 1; d < 1024; d <<= 1) {
        int a = (t >= d) ? s[t - d] : 0;
        __syncthreads();
        s[t] += a;
        __syncthreads();
    }
    if (i < N_NODES) g_off[i] = s[t] - v;
    if (t == 1023) g_bsum[blockIdx.x] = s[t];
}
__global__ void scan2_kernel() {
    __shared__ int s[256];
    int t = threadIdx.x;
    int v = (t < SCAN_BLKS) ? g_bsum[t] : 0;
    s[t] = v;
    __syncthreads();
    #pragma unroll
    for (int d = 1; d < 256; d <<= 1) {
        int a = (t >= d) ? s[t - d] : 0;
        __syncthreads();
        s[t] += a;
        __syncthreads();
    }
    g_boff[t] = s[t] - v;
}
__global__ void scan3_kernel() {
    int i = blockIdx.x * 1024 + threadIdx.x;
    if (i < N_NODES) {
        int o = g_off[i] + g_boff[blockIdx.x];
        g_off[i] = o;
        g_cur[i] = o;
    }
    if (i == 0) g_off[N_NODES] = N_EDGES;
}
__global__ void fill_kernel(const int* __restrict__ recv) {
    int e = blockIdx.x * blockDim.x + threadIdx.x;
    if (e < N_EDGES) {
        int pos = atomicAdd(&g_cur[recv[e]], 1);
        g_elist[pos] = e;
    }
}

// ---------------------------------------------------------------------------
// Fused kernel: 8 MLP warps + 2 gather warps per CTA (320 threads).
//   Gather warps produce g_agg for tile t+GRID while MLP warps consume tile t.
//   Sync: bar 1 (256 thr) = MLP-internal; bar 2 (320 thr) = tile boundary.
// ---------------------------------------------------------------------------
#define PITCH 136
#define AB_B  (128 * PITCH * 2)          // 34816
#define OFF_A0HI 0
#define OFF_A0LO (OFF_A0HI + AB_B)
#define OFF_A1HI (OFF_A0LO + AB_B)
#define OFF_A1LO (OFF_A1HI + AB_B)
#define OFF_STG  (OFF_A1LO + AB_B)       // fp32 128x128 = 65536
#define OFF_B1   (OFF_STG + 65536)
#define OFF_B2   (OFF_B1 + 512)
#define SMEM_SZ  (OFF_B2 + 512)          // 205824

__global__ __launch_bounds__(320, 1) void fused_mlp_kernel(
    const float* __restrict__ x,
    const float* __restrict__ edge_attr,
    const float* __restrict__ b1,
    const float* __restrict__ b2,
    float* __restrict__ out) {

    extern __shared__ char smem[];
    const uint32_t sb = smem_u32(smem);
    const int tid = threadIdx.x;
    const int lane = tid & 31;
    const int w = tid >> 5;              // 0..9
    const int mw = (w & 3) * 32;
    const int nwb = (w >> 2) * 8;        // MLP: n-block base (0 or 8)

    float* sB1 = (float*)(smem + OFF_B1);
    float* sB2 = (float*)(smem + OFF_B2);
    if (tid < 128) { sB1[tid] = b1[tid]; sB2[tid] = b2[tid]; }

    const int arow = lane & 15;
    const int acol = (lane >> 4) * 8;
    const int gr = tid >> 5;             // 0..7 for MLP threads
    const int gc = tid & 31;

    float acc[2][8][4];
    #pragma unroll
    for (int mt = 0; mt < 2; ++mt)
        #pragma unroll
        for (int nt = 0; nt < 8; ++nt)
            #pragma unroll
            for (int e = 0; e < 4; ++e) acc[mt][nt][e] = 0.f;

    auto stage_load = [&](const float* src, int node0, int V) {
        #pragma unroll
        for (int j = 0; j < 16; ++j) {
            int r = gr + j * 8;
            int rr = (r < V) ? r : (V - 1);
            cp_async16(sb + OFF_STG + (uint32_t)(r * 128 + gc * 4) * 4,
                       src + (size_t)(node0 + rr) * 128 + gc * 4);
        }
        CP_COMMIT();
    };
    auto convert_stage = [&](uint32_t dhi, uint32_t dlo) {
        #pragma unroll
        for (int j = 0; j < 16; ++j) {
            int r = gr + j * 8;
            float4 v = *(const float4*)(smem + OFF_STG + (r * 128 + gc * 4) * 4);
            uint32_t h0, l0, h1, l1;
            split2(v.x, v.y, h0, l0);
            split2(v.z, v.w, h1, l1);
            uint32_t off = (uint32_t)(r * PITCH + gc * 4) * 2;
            asm volatile("st.shared.v2.u32 [%0], {%1, %2};"
                         :: "r"(dhi + off), "r"(h0), "r"(h1));
            asm volatile("st.shared.v2.u32 [%0], {%1, %2};"
                         :: "r"(dlo + off), "r"(l0), "r"(l1));
        }
    };
    auto mma_step = [&](uint32_t ahiB, uint32_t aloB, const uint4* wf,
                        int ksg, int nks) {
        uint32_t ahi[2][4], alo[2][4];
        #pragma unroll
        for (int mt = 0; mt < 2; ++mt) {
            uint32_t aoff = (uint32_t)((mw + mt * 16 + arow) * PITCH +
                                       (ksg & 7) * 16 + acol) * 2;
            ldsm_x4(ahi[mt], ahiB + aoff);
            ldsm_x4(alo[mt], aloB + aoff);
        }
        uint4 f[8];
        #pragma unroll
        for (int nt = 0; nt < 8; ++nt)
            f[nt] = __ldg(&wf[((nwb + nt) * nks + ksg) * 32 + lane]);
        #pragma unroll
        for (int nt = 0; nt < 8; ++nt) {
            #pragma unroll
            for (int mt = 0; mt < 2; ++mt) {
                mma_bf16(acc[mt][nt], f[nt].x == f[nt].x ? ahi[mt] : ahi[mt], f[nt].x, f[nt].y),
                mma_bf16(acc[mt][nt], alo[mt], f[nt].x, f[nt].y);
                mma_bf16(acc[mt][nt], ahi[mt], f[nt].z, f[nt].w);
            }
        }
    };

    // ---- gather (warps 8,9): CSR gather-reduce one tile into g_agg ----
    const int gw = w - 8;
    auto gather_tile = [&](int node0g, int Vg) {
        int nbase = node0g + gw * 64;
        int navail = Vg - gw * 64;       // rows this warp owns (may be <= 0)
        #pragma unroll 1
        for (int c = 0; c < 8; ++c) {
            int n0 = c * 8;
            float4 a[8];
            int o[8], d[8];
            #pragma unroll
            for (int j = 0; j < 8; ++j) {
                a[j] = make_float4(0.f, 0.f, 0.f, 0.f);
                bool valid = (n0 + j) < navail;
                int node = valid ? (nbase + n0 + j) : 0;
                o[j] = __ldg(&g_off[node]);
                int o1 = __ldg(&g_off[node + 1]);
                d[j] = valid ? (o1 - o[j]) : 0;
            }
            int s0 = 0;
            while (true) {
                int e[8][4];
                #pragma unroll
                for (int j = 0; j < 8; ++j)
                    #pragma unroll
                    for (int s = 0; s < 4; ++s)
                        e[j][s] = (s0 + s < d[j]) ? __ldg(&g_elist[o[j] + s0 + s]) : -1;
                #pragma unroll
                for (int j = 0; j < 8; ++j)
                    #pragma unroll
                    for (int s = 0; s < 4; ++s)
                        if (e[j][s] >= 0) {
                            float4 v = __ldg((const float4*)edge_attr +
                                             (size_t)e[j][s] * 32 + lane);
                            a[j].x += v.x; a[j].y += v.y;
                            a[j].z += v.z; a[j].w += v.w;
                        }
                s0 += 4;
                bool more = false;
                #pragma unroll
                for (int j = 0; j < 8; ++j) more |= (d[j] > s0);
                if (!more) break;
            }
            #pragma unroll
            for (int j = 0; j < 8; ++j)
                if (n0 + j < navail)
                    ((float4*)g_agg)[(size_t)(nbase + n0 + j) * 32 + lane] = a[j];
        }
    };

    // ================= prologue =================
    int tile = blockIdx.x;
    if (w < 8) {
        if (tile < NT) stage_load(x, tile * 128, min(128, N_NODES - tile * 128));
    } else {
        if (tile < NT) gather_tile(tile * 128, min(128, N_NODES - tile * 128));
        __threadfence_block();
    }
    BARALL();   // biases + first agg tile published

    // ================= main loop =================
    for (; tile < NT; tile += GRID_MLP) {
        if (w >= 8) {
            // gather next tile while MLP warps process current one
            int tn = tile + GRID_MLP;
            if (tn < NT) gather_tile(tn * 128, min(128, N_NODES - tn * 128));
            __threadfence_block();
            BARALL();
            continue;
        }

        const int node0 = tile * 128;
        const int V = min(128, N_NODES - node0);
        const int tile_n = tile + GRID_MLP;
        const int node0n = (tile_n < NT) ? tile_n * 128 : 0;
        const int Vn = (tile_n < NT) ? min(128, N_NODES - node0n) : 128;

        CP_WAIT0();
        convert_stage(sb + OFF_A0HI, sb + OFF_A0LO);
        stage_load(g_agg, node0, V);            // agg(t) -> stage (async)
        BAR1();                                 // A0 visible

        #pragma unroll
        for (int ks = 0; ks < 4; ++ks)
            mma_step(sb + OFF_A0HI, sb + OFF_A0LO, g_W1f, ks, 16);
        CP_WAIT0();
        convert_stage(sb + OFF_A1HI, sb + OFF_A1LO);
        stage_load(x, node0n, Vn);
        #pragma unroll
        for (int ks = 4; ks < 8; ++ks)
            mma_step(sb + OFF_A0HI, sb + OFF_A0LO, g_W1f, ks, 16);
        BAR1();                                 // A1 visible

        #pragma unroll
        for (int ks = 0; ks < 8; ++ks)
            mma_step(sb + OFF_A1HI, sb + OFF_A1LO, g_W1f, 8 + ks, 16);

        // Epilogue 1: H = relu(acc + b1) -> A0 buffers
        {
            const int r0 = lane >> 2;
            const int c0 = 2 * (lane & 3);
            #pragma unroll
            for (int mt = 0; mt < 2; ++mt) {
                #pragma unroll
                for (int nt = 0; nt < 8; ++nt) {
                    int c = nwb * 8 + nt * 8 + c0;
                    float bb0 = sB1[c], bb1 = sB1[c + 1];
                    int rA = mw + mt * 16 + r0;
                    float h00 = fmaxf(acc[mt][nt][0] + bb0, 0.f);
                    float h01 = fmaxf(acc[mt][nt][1] + bb1, 0.f);
                    float h10 = fmaxf(acc[mt][nt][2] + bb0, 0.f);
                    float h11 = fmaxf(acc[mt][nt][3] + bb1, 0.f);
                    uint32_t hp0, lp0, hp1, lp1;
                    split2(h00, h01, hp0, lp0);
                    split2(h10, h11, hp1, lp1);
                    uint32_t o0 = (uint32_t)(rA * PITCH + c) * 2;
                    uint32_t o1 = (uint32_t)((rA + 8) * PITCH + c) * 2;
                    asm volatile("st.shared.b32 [%0], %1;" :: "r"(sb + OFF_A0HI + o0), "r"(hp0));
                    asm volatile("st.shared.b32 [%0], %1;" :: "r"(sb + OFF_A0LO + o0), "r"(lp0));
                    asm volatile("st.shared.b32 [%0], %1;" :: "r"(sb + OFF_A0HI + o1), "r"(hp1));
                    asm volatile("st.shared.b32 [%0], %1;" :: "r"(sb + OFF_A0LO + o1), "r"(lp1));
                    #pragma unroll
                    for (int e = 0; e < 4; ++e) acc[mt][nt][e] = 0.f;
                }
            }
        }
        BAR1();                                 // H visible

        #pragma unroll
        for (int ks = 0; ks < 8; ++ks)
            mma_step(sb + OFF_A0HI, sb + OFF_A0LO, g_W2f, ks, 8);

        // Epilogue 2: out = acc + b2
        {
            const int r0 = lane >> 2;
            const int c0 = 2 * (lane & 3);
            #pragma unroll
            for (int mt = 0; mt < 2; ++mt) {
                #pragma unroll
                for (int nt = 0; nt < 8; ++nt) {
                    int c = nwb * 8 + nt * 8 + c0;
                    float bb0 = sB2[c], bb1 = sB2[c + 1];
                    int r = mw + mt * 16 + r0;
                    if (r < V)
                        *(float2*)(out + (size_t)(node0 + r) * 128 + c) =
                            make_float2(acc[mt][nt][0] + bb0, acc[mt][nt][1] + bb1);
                    if (r + 8 < V)
                        *(float2*)(out + (size_t)(node0 + r + 8) * 128 + c) =
                            make_float2(acc[mt][nt][2] + bb0, acc[mt][nt][3] + bb1);
                    #pragma unroll
                    for (int e = 0; e < 4; ++e) acc[mt][nt][e] = 0.f;
                }
            }
        }
        BARALL();   // tile boundary: A-buffer reuse + agg(t+1) published
    }
}

// ---------------------------------------------------------------------------
extern "C" void kernel_launch(void* const* d_in, const int* in_sizes, int n_in,
                              void* d_out, int out_size) {
    const float* x          = (const float*)d_in[0];
    const float* edge_attr  = (const float*)d_in[1];
    const int*   edge_index = (const int*)d_in[2];   // int32
    const float* W1         = (const float*)d_in[3];
    const float* b1         = (const float*)d_in[4];
    const float* W2         = (const float*)d_in[5];
    const float* b2         = (const float*)d_in[6];
    float*       out        = (float*)d_out;

    const int* recv = edge_index + N_EDGES;

    cudaFuncSetAttribute(fused_mlp_kernel,
                         cudaFuncAttributeMaxDynamicSharedMemorySize, SMEM_SZ);

    prep_w_kernel<<<32, 256>>>(W1, W2);
    zero_hist_kernel<<<SCAN_BLKS, 1024>>>();
    hist_kernel<<<3125, 256>>>(recv);
    scan1_kernel<<<SCAN_BLKS, 1024>>>();
    scan2_kernel<<<1, 256>>>();
    scan3_kernel<<<SCAN_BLKS, 1024>>>();
    fill_kernel<<<3125, 256>>>(recv);
    fused_mlp_kernel<<<GRID_MLP, 320, SMEM_SZ>>>(x, edge_attr, b1, b2, out);
}

// round 16
// speedup vs baseline: 2.6137x; 2.6137x over previous
#include <cuda_runtime.h>
#include <cuda_fp16.h>
#include <cstdint>

#define N_NODES 200000
#define N_EDGES 800000
#define D 128
#define NT64 3125          // 200000 / 64 exactly
#define GRID_MLP 148
#define NGROUPS 296        // 148 CTAs * 2 groups
#define SCAN_BLKS 196      // ceil(200000/1024)

// ---------------------------------------------------------------------------
// Device scratch (allocation-free rule).
// ---------------------------------------------------------------------------
__device__ float g_agg[(size_t)N_NODES * D];
// CSR for edge->receiver gather
__device__ int g_hist[N_NODES];
__device__ int g_off[N_NODES + 1];
__device__ int g_cur[N_NODES];
__device__ int g_elist[N_EDGES];
__device__ int g_bsum[256];
__device__ int g_boff[256];
// Fragment-major fp16 weights (hi only): uint2 = {b0, b1} per (nb, ks, lane)
__device__ uint2 g_W1f[16 * 16 * 32];   // [nb][ksg 0..15][lane]
__device__ uint2 g_W2f[16 * 8 * 32];    // [nb][ksg 0..7][lane]

// ---------------------------------------------------------------------------
// helpers
// ---------------------------------------------------------------------------
__device__ __forceinline__ uint32_t smem_u32(const void* p) {
    uint32_t a;
    asm("{ .reg .u64 t; cvta.to.shared.u64 t, %1; cvt.u32.u64 %0, t; }"
        : "=r"(a) : "l"(p));
    return a;
}
// pack two floats to fp16x2 (lo element = first arg)
__device__ __forceinline__ uint32_t pack_h2(float lo, float hi) {
    uint32_t r;
    asm("cvt.rn.f16x2.f32 %0, %1, %2;" : "=r"(r) : "f"(hi), "f"(lo));
    return r;
}
// split two floats into fp16 hi pair + fp16 residual pair
__device__ __forceinline__ void split2h(float v0, float v1,
                                        uint32_t& hp, uint32_t& lp) {
    hp = pack_h2(v0, v1);
    __half2 h = *reinterpret_cast<__half2*>(&hp);
    float2 hf = __half22float2(h);
    lp = pack_h2(v0 - hf.x, v1 - hf.y);
}
__device__ __forceinline__ void ldsm_x4(uint32_t (&r)[4], uint32_t addr) {
    asm volatile("ldmatrix.sync.aligned.m8n8.x4.shared.b16 {%0,%1,%2,%3}, [%4];"
                 : "=r"(r[0]), "=r"(r[1]), "=r"(r[2]), "=r"(r[3]) : "r"(addr));
}
__device__ __forceinline__ void mma_f16(float (&d)[4], const uint32_t (&a)[4],
                                        uint32_t b0, uint32_t b1) {
    asm volatile(
        "mma.sync.aligned.m16n8k16.row.col.f32.f16.f16.f32 "
        "{%0,%1,%2,%3}, {%4,%5,%6,%7}, {%8,%9}, {%0,%1,%2,%3};"
        : "+f"(d[0]), "+f"(d[1]), "+f"(d[2]), "+f"(d[3])
        : "r"(a[0]), "r"(a[1]), "r"(a[2]), "r"(a[3]), "r"(b0), "r"(b1));
}
__device__ __forceinline__ void cp_async16(uint32_t dst, const void* src) {
    asm volatile("cp.async.ca.shared.global [%0], [%1], 16;"
                 :: "r"(dst), "l"(src) : "memory");
}
#define CP_COMMIT() asm volatile("cp.async.commit_group;" ::: "memory")
#define CP_WAIT0()  asm volatile("cp.async.wait_group 0;" ::: "memory")
#define BARG(id) asm volatile("bar.sync %0, 256;" :: "r"(id) : "memory")

// ---------------------------------------------------------------------------
// Kernel 0: fragment-major fp16 weights (hi only; W rounding = 2^-11 rel).
// ---------------------------------------------------------------------------
__global__ void prep_w_kernel(const float* __restrict__ W1,
                              const float* __restrict__ W2) {
    int i = blockIdx.x * blockDim.x + threadIdx.x;
    if (i < 8192) {                       // W1: 16 nb x 16 ks x 32 lanes
        int lane = i & 31, ks = (i >> 5) & 15, nb = i >> 9;
        int n = nb * 8 + (lane >> 2);
        int k0 = ks * 16 + 2 * (lane & 3);
        float v00 = W1[(k0 + 0) * 128 + n], v01 = W1[(k0 + 1) * 128 + n];
        float v10 = W1[(k0 + 8) * 128 + n], v11 = W1[(k0 + 9) * 128 + n];
        g_W1f[i] = make_uint2(pack_h2(v00, v01), pack_h2(v10, v11));
    }
    if (i < 4096) {                       // W2: 16 nb x 8 ks x 32 lanes
        int lane = i & 31, ks = (i >> 5) & 7, nb = i >> 8;
        int n = nb * 8 + (lane >> 2);
        int k0 = ks * 16 + 2 * (lane & 3);
        float v00 = W2[(k0 + 0) * 128 + n], v01 = W2[(k0 + 1) * 128 + n];
        float v10 = W2[(k0 + 8) * 128 + n], v11 = W2[(k0 + 9) * 128 + n];
        g_W2f[i] = make_uint2(pack_h2(v00, v01), pack_h2(v10, v11));
    }
}

// ---------------------------------------------------------------------------
// CSR build: zero hist -> histogram -> scan -> fill.
// ---------------------------------------------------------------------------
__global__ void zero_hist_kernel() {
    int i = blockIdx.x * 1024 + threadIdx.x;
    if (i < N_NODES) g_hist[i] = 0;
}
__global__ void hist_kernel(const int* __restrict__ recv) {
    int e = blockIdx.x * blockDim.x + threadIdx.x;
    if (e < N_EDGES) atomicAdd(&g_hist[recv[e]], 1);
}
__global__ void scan1_kernel() {
    __shared__ int s[1024];
    int t = threadIdx.x;
    int i = blockIdx.x * 1024 + t;
    int v = (i < N_NODES) ? g_hist[i] : 0;
    s[t] = v;
    __syncthreads();
    #pragma unroll
    for (int d = 1; d < 1024; d <<= 1) {
        int a = (t >= d) ? s[t - d] : 0;
        __syncthreads();
        s[t] += a;
        __syncthreads();
    }
    if (i < N_NODES) g_off[i] = s[t] - v;
    if (t == 1023) g_bsum[blockIdx.x] = s[t];
}
__global__ void scan2_kernel() {
    __shared__ int s[256];
    int t = threadIdx.x;
    int v = (t < SCAN_BLKS) ? g_bsum[t] : 0;
    s[t] = v;
    __syncthreads();
    #pragma unroll
    for (int d = 1; d < 256; d <<= 1) {
        int a = (t >= d) ? s[t - d] : 0;
        __syncthreads();
        s[t] += a;
        __syncthreads();
    }
    g_boff[t] = s[t] - v;
}
__global__ void scan3_kernel() {
    int i = blockIdx.x * 1024 + threadIdx.x;
    if (i < N_NODES) {
        int o = g_off[i] + g_boff[blockIdx.x];
        g_off[i] = o;
        g_cur[i] = o;
    }
    if (i == 0) g_off[N_NODES] = N_EDGES;
}
__global__ void fill_kernel(const int* __restrict__ recv) {
    int e = blockIdx.x * blockDim.x + threadIdx.x;
    if (e < N_EDGES) {
        int pos = atomicAdd(&g_cur[recv[e]], 1);
        g_elist[pos] = e;
    }
}

// ---------------------------------------------------------------------------
// Kernel 2b: gather-reduce edge rows into g_agg. One warp per node.
// ---------------------------------------------------------------------------
__global__ __launch_bounds__(256) void gather_kernel(
    const float* __restrict__ edge_attr) {
    int warp = (blockIdx.x * 256 + threadIdx.x) >> 5;
    int lane = threadIdx.x & 31;
    if (warp >= N_NODES) return;
    int o0 = __ldg(&g_off[warp]);
    int o1 = __ldg(&g_off[warp + 1]);
    float4 a = make_float4(0.f, 0.f, 0.f, 0.f);
    int t = o0;
    for (; t + 4 <= o1; t += 4) {
        int e0 = __ldg(&g_elist[t + 0]);
        int e1 = __ldg(&g_elist[t + 1]);
        int e2 = __ldg(&g_elist[t + 2]);
        int e3 = __ldg(&g_elist[t + 3]);
        float4 v0 = *((const float4*)edge_attr + (size_t)e0 * 32 + lane);
        float4 v1 = *((const float4*)edge_attr + (size_t)e1 * 32 + lane);
        float4 v2 = *((const float4*)edge_attr + (size_t)e2 * 32 + lane);
        float4 v3 = *((const float4*)edge_attr + (size_t)e3 * 32 + lane);
        a.x += v0.x + v1.x + v2.x + v3.x;
        a.y += v0.y + v1.y + v2.y + v3.y;
        a.z += v0.z + v1.z + v2.z + v3.z;
        a.w += v0.w + v1.w + v2.w + v3.w;
    }
    for (; t < o1; ++t) {
        int e0 = __ldg(&g_elist[t]);
        float4 v0 = *((const float4*)edge_attr + (size_t)e0 * 32 + lane);
        a.x += v0.x; a.y += v0.y; a.z += v0.z; a.w += v0.w;
    }
    ((float4*)g_agg)[(size_t)warp * 32 + lane] = a;
}

// ---------------------------------------------------------------------------
// Kernel 3: split-CTA pipelined fp16 2-term MLP.
//   512 threads = 2 independent groups of 256 (8 warps each), private smem,
//   group-local named barriers -> groups drift out of phase, overlapping one
//   group's loads/epilogues with the other's HMMA stream.
//   2-term: D = Ahi*Wh + Alo*Wh  (A split exactly; W rounded once to fp16).
// ---------------------------------------------------------------------------
#define PITCH 136
#define AB64  (64 * PITCH * 2)           // 17408
#define GRP_B (4 * AB64 + 64 * 128 * 4)  // A0/A1 hi+lo + fp32 stage = 102400
#define OFF_STG (4 * AB64)
#define OFF_B1  (2 * GRP_B)              // 204800
#define OFF_B2  (OFF_B1 + 512)
#define SMEM_SZ (OFF_B2 + 512)           // 205824

__global__ __launch_bounds__(512, 1) void mma_mlp_kernel(
    const float* __restrict__ x,
    const float* __restrict__ b1,
    const float* __restrict__ b2,
    float* __restrict__ out) {

    extern __shared__ char smem[];
    const int tid = threadIdx.x;
    const int g = tid >> 8;              // group 0/1
    const int gtid = tid & 255;
    const int lane = tid & 31;
    const int wg = gtid >> 5;            // warp in group (0..7)
    const int mw = (wg & 1) * 32;        // M band within 64 rows
    const int nwb = (wg >> 1) * 4;       // n-block base (4 blocks of 8 cols)
    const int barid = g + 1;

    const uint32_t gb = smem_u32(smem) + g * GRP_B;
    const uint32_t A0HI = gb, A0LO = gb + AB64;
    const uint32_t A1HI = gb + 2 * AB64, A1LO = gb + 3 * AB64;
    const uint32_t STG = gb + OFF_STG;
    float* sB1 = (float*)(smem + OFF_B1);
    float* sB2 = (float*)(smem + OFF_B2);
    if (tid < 128) { sB1[tid] = b1[tid]; sB2[tid] = b2[tid]; }
    __syncthreads();   // biases visible to both groups (barrier 0, once)

    const int arow = lane & 15;
    const int acol = (lane >> 4) * 8;
    const int gr = gtid >> 5;            // 0..7
    const int gc = gtid & 31;

    float acc[2][4][4];
    #pragma unroll
    for (int mt = 0; mt < 2; ++mt)
        #pragma unroll
        for (int nt = 0; nt < 4; ++nt)
            #pragma unroll
            for (int e = 0; e < 4; ++e) acc[mt][nt][e] = 0.f;

    auto stage_load = [&](const float* src, int node0) {
        #pragma unroll
        for (int j = 0; j < 8; ++j) {
            int r = gr + j * 8;          // 0..63
            cp_async16(STG + (uint32_t)(r * 128 + gc * 4) * 4,
                       src + (size_t)(node0 + r) * 128 + gc * 4);
        }
        CP_COMMIT();
    };
    auto convert_stage = [&](uint32_t dhi, uint32_t dlo) {
        #pragma unroll
        for (int j = 0; j < 8; ++j) {
            int r = gr + j * 8;
            float4 v = *(const float4*)((const char*)smem +
                        (STG - smem_u32(smem)) + (r * 128 + gc * 4) * 4);
            uint32_t h0, l0, h1, l1;
            split2h(v.x, v.y, h0, l0);
            split2h(v.z, v.w, h1, l1);
            uint32_t off = (uint32_t)(r * PITCH + gc * 4) * 2;
            asm volatile("st.shared.v2.u32 [%0], {%1, %2};"
                         :: "r"(dhi + off), "r"(h0), "r"(h1));
            asm volatile("st.shared.v2.u32 [%0], {%1, %2};"
                         :: "r"(dlo + off), "r"(l0), "r"(l1));
        }
    };
    auto mma_step = [&](uint32_t ahiB, uint32_t aloB, const uint2* wf,
                        int ksg, int nks) {
        uint32_t ahi[2][4], alo[2][4];
        #pragma unroll
        for (int mt = 0; mt < 2; ++mt) {
            uint32_t aoff = (uint32_t)((mw + mt * 16 + arow) * PITCH +
                                       (ksg & 7) * 16 + acol) * 2;
            ldsm_x4(ahi[mt], ahiB + aoff);
            ldsm_x4(alo[mt], aloB + aoff);
        }
        #pragma unroll
        for (int nt = 0; nt < 4; ++nt) {
            uint2 f = __ldg(&wf[((nwb + nt) * nks + ksg) * 32 + lane]);
            #pragma unroll
            for (int mt = 0; mt < 2; ++mt) {
                mma_f16(acc[mt][nt], ahi[mt], f.x, f.y);
                mma_f16(acc[mt][nt], alo[mt], f.x, f.y);
            }
        }
    };

    const int gg = blockIdx.x * 2 + g;   // global group id 0..295
    int tile = gg;
    stage_load(x, tile * 64);            // prologue: x(t0)

    for (; tile < NT64; tile += NGROUPS) {
        const int node0 = tile * 64;
        const int tile_n = tile + NGROUPS;
        const int node0n = (tile_n < NT64) ? tile_n * 64 : 0;

        CP_WAIT0();
        convert_stage(A0HI, A0LO);
        stage_load(g_agg, node0);               // agg -> stage (async)
        BARG(barid);                            // A0 visible

        #pragma unroll
        for (int ks = 0; ks < 4; ++ks)
            mma_step(A0HI, A0LO, g_W1f, ks, 16);
        CP_WAIT0();
        convert_stage(A1HI, A1LO);
        stage_load(x, node0n);                  // x(t+1)
        #pragma unroll
        for (int ks = 4; ks < 8; ++ks)
            mma_step(A0HI, A0LO, g_W1f, ks, 16);
        BARG(barid);                            // A1 visible

        #pragma unroll
        for (int ks = 0; ks < 8; ++ks)
            mma_step(A1HI, A1LO, g_W1f, 8 + ks, 16);

        // Epilogue 1: H = relu(acc + b1) -> A0 buffers (fp16 hi/lo)
        {
            const int r0 = lane >> 2;
            const int c0 = 2 * (lane & 3);
            #pragma unroll
            for (int mt = 0; mt < 2; ++mt) {
                #pragma unroll
                for (int nt = 0; nt < 4; ++nt) {
                    int c = nwb * 8 + nt * 8 + c0;
                    float bb0 = sB1[c], bb1 = sB1[c + 1];
                    int rA = mw + mt * 16 + r0;
                    float h00 = fmaxf(acc[mt][nt][0] + bb0, 0.f);
                    float h01 = fmaxf(acc[mt][nt][1] + bb1, 0.f);
                    float h10 = fmaxf(acc[mt][nt][2] + bb0, 0.f);
                    float h11 = fmaxf(acc[mt][nt][3] + bb1, 0.f);
                    uint32_t hp0, lp0, hp1, lp1;
                    split2h(h00, h01, hp0, lp0);
                    split2h(h10, h11, hp1, lp1);
                    uint32_t o0 = (uint32_t)(rA * PITCH + c) * 2;
                    uint32_t o1 = (uint32_t)((rA + 8) * PITCH + c) * 2;
                    asm volatile("st.shared.b32 [%0], %1;" :: "r"(A0HI + o0), "r"(hp0));
                    asm volatile("st.shared.b32 [%0], %1;" :: "r"(A0LO + o0), "r"(lp0));
                    asm volatile("st.shared.b32 [%0], %1;" :: "r"(A0HI + o1), "r"(hp1));
                    asm volatile("st.shared.b32 [%0], %1;" :: "r"(A0LO + o1), "r"(lp1));
                    #pragma unroll
                    for (int e = 0; e < 4; ++e) acc[mt][nt][e] = 0.f;
                }
            }
        }
        BARG(barid);                            // H visible (cross-warp cols)

        #pragma unroll
        for (int ks = 0; ks < 8; ++ks)
            mma_step(A0HI, A0LO, g_W2f, ks, 8);

        // Epilogue 2: out = acc + b2  (tiles always full: V = 64)
        {
            const int r0 = lane >> 2;
            const int c0 = 2 * (lane & 3);
            #pragma unroll
            for (int mt = 0; mt < 2; ++mt) {
                #pragma unroll
                for (int nt = 0; nt < 4; ++nt) {
                    int c = nwb * 8 + nt * 8 + c0;
                    float bb0 = sB2[c], bb1 = sB2[c + 1];
                    int r = mw + mt * 16 + r0;
                    *(float2*)(out + (size_t)(node0 + r) * 128 + c) =
                        make_float2(acc[mt][nt][0] + bb0, acc[mt][nt][1] + bb1);
                    *(float2*)(out + (size_t)(node0 + r + 8) * 128 + c) =
                        make_float2(acc[mt][nt][2] + bb0, acc[mt][nt][3] + bb1);
                    #pragma unroll
                    for (int e = 0; e < 4; ++e) acc[mt][nt][e] = 0.f;
                }
            }
        }
        BARG(barid);   // all reads of A0/A1 done before next tile writes
    }
}

// ---------------------------------------------------------------------------
extern "C" void kernel_launch(void* const* d_in, const int* in_sizes, int n_in,
                              void* d_out, int out_size) {
    const float* x          = (const float*)d_in[0];
    const float* edge_attr  = (const float*)d_in[1];
    const int*   edge_index = (const int*)d_in[2];   // int32
    const float* W1         = (const float*)d_in[3];
    const float* b1         = (const float*)d_in[4];
    const float* W2         = (const float*)d_in[5];
    const float* b2         = (const float*)d_in[6];
    float*       out        = (float*)d_out;

    const int* recv = edge_index + N_EDGES;

    cudaFuncSetAttribute(mma_mlp_kernel,
                         cudaFuncAttributeMaxDynamicSharedMemorySize, SMEM_SZ);

    prep_w_kernel<<<32, 256>>>(W1, W2);
    zero_hist_kernel<<<SCAN_BLKS, 1024>>>();
    hist_kernel<<<3125, 256>>>(recv);
    scan1_kernel<<<SCAN_BLKS, 1024>>>();
    scan2_kernel<<<1, 256>>>();
    scan3_kernel<<<SCAN_BLKS, 1024>>>();
    fill_kernel<<<3125, 256>>>(recv);
    gather_kernel<<<25000, 256>>>(edge_attr);
    mma_mlp_kernel<<<GRID_MLP, 512, SMEM_SZ>>>(x, b1, b2, out);
}

// round 17
// speedup vs baseline: 2.8914x; 1.1062x over previous
#include <cuda_runtime.h>
#include <cuda_fp16.h>
#include <cstdint>

#define N_NODES 200000
#define N_EDGES 800000
#define D 128
#define NT64 3125          // 200000 / 64 exactly
#define GRID_MLP 148
#define NGROUPS 296        // 148 CTAs * 2 groups
#define SCAN_BLKS 196      // ceil(200000/1024)

// ---------------------------------------------------------------------------
// Device scratch (allocation-free rule).
// ---------------------------------------------------------------------------
__device__ float g_agg[(size_t)N_NODES * D];
// CSR for edge->receiver gather
__device__ int g_hist[N_NODES];
__device__ int g_off[N_NODES + 1];
__device__ int g_cur[N_NODES];
__device__ int g_elist[N_EDGES];
__device__ int g_bsum[256];
__device__ int g_boff[256];
// Fragment-major fp16 weights: uint2 = {b0, b1} per (nb, ks, lane)
__device__ uint2 g_W1f[16 * 16 * 32];   // [nb][ksg 0..15][lane]
__device__ uint2 g_W2f[16 * 8 * 32];    // [nb][ksg 0..7][lane]

// ---------------------------------------------------------------------------
// helpers
// ---------------------------------------------------------------------------
__device__ __forceinline__ uint32_t smem_u32(const void* p) {
    uint32_t a;
    asm("{ .reg .u64 t; cvta.to.shared.u64 t, %1; cvt.u32.u64 %0, t; }"
        : "=r"(a) : "l"(p));
    return a;
}
// pack two floats to fp16x2 (lo element = first arg)
__device__ __forceinline__ uint32_t pack_h2(float lo, float hi) {
    uint32_t r;
    asm("cvt.rn.f16x2.f32 %0, %1, %2;" : "=r"(r) : "f"(hi), "f"(lo));
    return r;
}
__device__ __forceinline__ void ldsm_x4(uint32_t (&r)[4], uint32_t addr) {
    asm volatile("ldmatrix.sync.aligned.m8n8.x4.shared.b16 {%0,%1,%2,%3}, [%4];"
                 : "=r"(r[0]), "=r"(r[1]), "=r"(r[2]), "=r"(r[3]) : "r"(addr));
}
__device__ __forceinline__ void mma_f16(float (&d)[4], const uint32_t (&a)[4],
                                        uint32_t b0, uint32_t b1) {
    asm volatile(
        "mma.sync.aligned.m16n8k16.row.col.f32.f16.f16.f32 "
        "{%0,%1,%2,%3}, {%4,%5,%6,%7}, {%8,%9}, {%0,%1,%2,%3};"
        : "+f"(d[0]), "+f"(d[1]), "+f"(d[2]), "+f"(d[3])
        : "r"(a[0]), "r"(a[1]), "r"(a[2]), "r"(a[3]), "r"(b0), "r"(b1));
}
__device__ __forceinline__ void cp_async16(uint32_t dst, const void* src) {
    asm volatile("cp.async.ca.shared.global [%0], [%1], 16;"
                 :: "r"(dst), "l"(src) : "memory");
}
#define CP_COMMIT() asm volatile("cp.async.commit_group;" ::: "memory")
#define CP_WAIT0()  asm volatile("cp.async.wait_group 0;" ::: "memory")
#define BARG(id) asm volatile("bar.sync %0, 256;" :: "r"(id) : "memory")

// ---------------------------------------------------------------------------
// Kernel 0: fragment-major fp16 weights.
// ---------------------------------------------------------------------------
__global__ void prep_w_kernel(const float* __restrict__ W1,
                              const float* __restrict__ W2) {
    int i = blockIdx.x * blockDim.x + threadIdx.x;
    if (i < 8192) {                       // W1: 16 nb x 16 ks x 32 lanes
        int lane = i & 31, ks = (i >> 5) & 15, nb = i >> 9;
        int n = nb * 8 + (lane >> 2);
        int k0 = ks * 16 + 2 * (lane & 3);
        float v00 = W1[(k0 + 0) * 128 + n], v01 = W1[(k0 + 1) * 128 + n];
        float v10 = W1[(k0 + 8) * 128 + n], v11 = W1[(k0 + 9) * 128 + n];
        g_W1f[i] = make_uint2(pack_h2(v00, v01), pack_h2(v10, v11));
    }
    if (i < 4096) {                       // W2: 16 nb x 8 ks x 32 lanes
        int lane = i & 31, ks = (i >> 5) & 7, nb = i >> 8;
        int n = nb * 8 + (lane >> 2);
        int k0 = ks * 16 + 2 * (lane & 3);
        float v00 = W2[(k0 + 0) * 128 + n], v01 = W2[(k0 + 1) * 128 + n];
        float v10 = W2[(k0 + 8) * 128 + n], v11 = W2[(k0 + 9) * 128 + n];
        g_W2f[i] = make_uint2(pack_h2(v00, v01), pack_h2(v10, v11));
    }
}

// ---------------------------------------------------------------------------
// CSR build: zero hist -> histogram -> scan -> fill.
// ---------------------------------------------------------------------------
__global__ void zero_hist_kernel() {
    int i = blockIdx.x * 1024 + threadIdx.x;
    if (i < N_NODES) g_hist[i] = 0;
}
__global__ void hist_kernel(const int* __restrict__ recv) {
    int e = blockIdx.x * blockDim.x + threadIdx.x;
    if (e < N_EDGES) atomicAdd(&g_hist[recv[e]], 1);
}
__global__ void scan1_kernel() {
    __shared__ int s[1024];
    int t = threadIdx.x;
    int i = blockIdx.x * 1024 + t;
    int v = (i < N_NODES) ? g_hist[i] : 0;
    s[t] = v;
    __syncthreads();
    #pragma unroll
    for (int d = 1; d < 1024; d <<= 1) {
        int a = (t >= d) ? s[t - d] : 0;
        __syncthreads();
        s[t] += a;
        __syncthreads();
    }
    if (i < N_NODES) g_off[i] = s[t] - v;
    if (t == 1023) g_bsum[blockIdx.x] = s[t];
}
__global__ void scan2_kernel() {
    __shared__ int s[256];
    int t = threadIdx.x;
    int v = (t < SCAN_BLKS) ? g_bsum[t] : 0;
    s[t] = v;
    __syncthreads();
    #pragma unroll
    for (int d = 1; d < 256; d <<= 1) {
        int a = (t >= d) ? s[t - d] : 0;
        __syncthreads();
        s[t] += a;
        __syncthreads();
    }
    g_boff[t] = s[t] - v;
}
__global__ void scan3_kernel() {
    int i = blockIdx.x * 1024 + threadIdx.x;
    if (i < N_NODES) {
        int o = g_off[i] + g_boff[blockIdx.x];
        g_off[i] = o;
        g_cur[i] = o;
    }
    if (i == 0) g_off[N_NODES] = N_EDGES;
}
__global__ void fill_kernel(const int* __restrict__ recv) {
    int e = blockIdx.x * blockDim.x + threadIdx.x;
    if (e < N_EDGES) {
        int pos = atomicAdd(&g_cur[recv[e]], 1);
        g_elist[pos] = e;
    }
}

// ---------------------------------------------------------------------------
// Kernel 2b: gather-reduce edge rows into g_agg. One warp per node.
// ---------------------------------------------------------------------------
__global__ __launch_bounds__(256) void gather_kernel(
    const float* __restrict__ edge_attr) {
    int warp = (blockIdx.x * 256 + threadIdx.x) >> 5;
    int lane = threadIdx.x & 31;
    if (warp >= N_NODES) return;
    int o0 = __ldg(&g_off[warp]);
    int o1 = __ldg(&g_off[warp + 1]);
    float4 a = make_float4(0.f, 0.f, 0.f, 0.f);
    int t = o0;
    for (; t + 4 <= o1; t += 4) {
        int e0 = __ldg(&g_elist[t + 0]);
        int e1 = __ldg(&g_elist[t + 1]);
        int e2 = __ldg(&g_elist[t + 2]);
        int e3 = __ldg(&g_elist[t + 3]);
        float4 v0 = *((const float4*)edge_attr + (size_t)e0 * 32 + lane);
        float4 v1 = *((const float4*)edge_attr + (size_t)e1 * 32 + lane);
        float4 v2 = *((const float4*)edge_attr + (size_t)e2 * 32 + lane);
        float4 v3 = *((const float4*)edge_attr + (size_t)e3 * 32 + lane);
        a.x += v0.x + v1.x + v2.x + v3.x;
        a.y += v0.y + v1.y + v2.y + v3.y;
        a.z += v0.z + v1.z + v2.z + v3.z;
        a.w += v0.w + v1.w + v2.w + v3.w;
    }
    for (; t < o1; ++t) {
        int e0 = __ldg(&g_elist[t]);
        float4 v0 = *((const float4*)edge_attr + (size_t)e0 * 32 + lane);
        a.x += v0.x; a.y += v0.y; a.z += v0.z; a.w += v0.w;
    }
    ((float4*)g_agg)[(size_t)warp * 32 + lane] = a;
}

// ---------------------------------------------------------------------------
// Kernel 3: split-CTA pipelined PURE fp16 MLP (1 term).
//   512 threads = 2 independent groups of 256 (8 warps each), private smem,
//   group-local named barriers. A (x/agg/H) rounded once to fp16; W fp16.
//   Per step per warp: 2 LDSM.x4 + 4 LDG.64 + 8 HMMA.
// ---------------------------------------------------------------------------
#define PITCH 136
#define AB64  (64 * PITCH * 2)           // 17408
#define GRP_B (2 * AB64 + 64 * 128 * 4)  // A0 + A1 + fp32 stage = 67584
#define OFF_STG (2 * AB64)
#define OFF_B1  (2 * GRP_B)              // 135168
#define OFF_B2  (OFF_B1 + 512)
#define SMEM_SZ (OFF_B2 + 512)           // 136192

__global__ __launch_bounds__(512, 1) void mma_mlp_kernel(
    const float* __restrict__ x,
    const float* __restrict__ b1,
    const float* __restrict__ b2,
    float* __restrict__ out) {

    extern __shared__ char smem[];
    const int tid = threadIdx.x;
    const int g = tid >> 8;              // group 0/1
    const int gtid = tid & 255;
    const int lane = tid & 31;
    const int wg = gtid >> 5;            // warp in group (0..7)
    const int mw = (wg & 1) * 32;        // M band within 64 rows
    const int nwb = (wg >> 1) * 4;       // n-block base (4 blocks of 8 cols)
    const int barid = g + 1;

    const uint32_t gb = smem_u32(smem) + g * GRP_B;
    const uint32_t A0 = gb;
    const uint32_t A1 = gb + AB64;
    const uint32_t STG = gb + OFF_STG;
    float* sB1 = (float*)(smem + OFF_B1);
    float* sB2 = (float*)(smem + OFF_B2);
    if (tid < 128) { sB1[tid] = b1[tid]; sB2[tid] = b2[tid]; }
    __syncthreads();   // biases visible to both groups (barrier 0, once)

    const int arow = lane & 15;
    const int acol = (lane >> 4) * 8;
    const int gr = gtid >> 5;            // 0..7
    const int gc = gtid & 31;

    float acc[2][4][4];
    #pragma unroll
    for (int mt = 0; mt < 2; ++mt)
        #pragma unroll
        for (int nt = 0; nt < 4; ++nt)
            #pragma unroll
            for (int e = 0; e < 4; ++e) acc[mt][nt][e] = 0.f;

    auto stage_load = [&](const float* src, int node0) {
        #pragma unroll
        for (int j = 0; j < 8; ++j) {
            int r = gr + j * 8;          // 0..63
            cp_async16(STG + (uint32_t)(r * 128 + gc * 4) * 4,
                       src + (size_t)(node0 + r) * 128 + gc * 4);
        }
        CP_COMMIT();
    };
    auto convert_stage = [&](uint32_t dst) {
        #pragma unroll
        for (int j = 0; j < 8; ++j) {
            int r = gr + j * 8;
            float4 v = *(const float4*)((const char*)smem +
                        (STG - smem_u32(smem)) + (r * 128 + gc * 4) * 4);
            uint32_t h0 = pack_h2(v.x, v.y);
            uint32_t h1 = pack_h2(v.z, v.w);
            uint32_t off = (uint32_t)(r * PITCH + gc * 4) * 2;
            asm volatile("st.shared.v2.u32 [%0], {%1, %2};"
                         :: "r"(dst + off), "r"(h0), "r"(h1));
        }
    };
    auto mma_step = [&](uint32_t aB, const uint2* wf, int ksg, int nks) {
        uint32_t a[2][4];
        #pragma unroll
        for (int mt = 0; mt < 2; ++mt) {
            uint32_t aoff = (uint32_t)((mw + mt * 16 + arow) * PITCH +
                                       (ksg & 7) * 16 + acol) * 2;
            ldsm_x4(a[mt], aB + aoff);
        }
        #pragma unroll
        for (int nt = 0; nt < 4; ++nt) {
            uint2 f = __ldg(&wf[((nwb + nt) * nks + ksg) * 32 + lane]);
            #pragma unroll
            for (int mt = 0; mt < 2; ++mt)
                mma_f16(acc[mt][nt], a[mt], f.x, f.y);
        }
    };

    const int gg = blockIdx.x * 2 + g;   // global group id 0..295
    int tile = gg;
    stage_load(x, tile * 64);            // prologue: x(t0)

    for (; tile < NT64; tile += NGROUPS) {
        const int node0 = tile * 64;
        const int tile_n = tile + NGROUPS;
        const int node0n = (tile_n < NT64) ? tile_n * 64 : 0;

        CP_WAIT0();
        convert_stage(A0);
        stage_load(g_agg, node0);               // agg -> stage (async)
        BARG(barid);                            // A0 visible

        #pragma unroll
        for (int ks = 0; ks < 4; ++ks)
            mma_step(A0, g_W1f, ks, 16);
        CP_WAIT0();
        convert_stage(A1);
        stage_load(x, node0n);                  // x(t+1)
        #pragma unroll
        for (int ks = 4; ks < 8; ++ks)
            mma_step(A0, g_W1f, ks, 16);
        BARG(barid);                            // A1 visible

        #pragma unroll
        for (int ks = 0; ks < 8; ++ks)
            mma_step(A1, g_W1f, 8 + ks, 16);

        // Epilogue 1: H = relu(acc + b1) -> A0 (fp16)
        {
            const int r0 = lane >> 2;
            const int c0 = 2 * (lane & 3);
            #pragma unroll
            for (int mt = 0; mt < 2; ++mt) {
                #pragma unroll
                for (int nt = 0; nt < 4; ++nt) {
                    int c = nwb * 8 + nt * 8 + c0;
                    float bb0 = sB1[c], bb1 = sB1[c + 1];
                    int rA = mw + mt * 16 + r0;
                    float h00 = fmaxf(acc[mt][nt][0] + bb0, 0.f);
                    float h01 = fmaxf(acc[mt][nt][1] + bb1, 0.f);
                    float h10 = fmaxf(acc[mt][nt][2] + bb0, 0.f);
                    float h11 = fmaxf(acc[mt][nt][3] + bb1, 0.f);
                    uint32_t hp0 = pack_h2(h00, h01);
                    uint32_t hp1 = pack_h2(h10, h11);
                    uint32_t o0 = (uint32_t)(rA * PITCH + c) * 2;
                    uint32_t o1 = (uint32_t)((rA + 8) * PITCH + c) * 2;
                    asm volatile("st.shared.b32 [%0], %1;" :: "r"(A0 + o0), "r"(hp0));
                    asm volatile("st.shared.b32 [%0], %1;" :: "r"(A0 + o1), "r"(hp1));
                    #pragma unroll
                    for (int e = 0; e < 4; ++e) acc[mt][nt][e] = 0.f;
                }
            }
        }
        BARG(barid);                            // H visible (cross-warp cols)

        #pragma unroll
        for (int ks = 0; ks < 8; ++ks)
            mma_step(A0, g_W2f, ks, 8);

        // Epilogue 2: out = acc + b2  (tiles always full: V = 64)
        {
            const int r0 = lane >> 2;
            const int c0 = 2 * (lane & 3);
            #pragma unroll
            for (int mt = 0; mt < 2; ++mt) {
                #pragma unroll
                for (int nt = 0; nt < 4; ++nt) {
                    int c = nwb * 8 + nt * 8 + c0;
                    float bb0 = sB2[c], bb1 = sB2[c + 1];
                    int r = mw + mt * 16 + r0;
                    *(float2*)(out + (size_t)(node0 + r) * 128 + c) =
                        make_float2(acc[mt][nt][0] + bb0, acc[mt][nt][1] + bb1);
                    *(float2*)(out + (size_t)(node0 + r + 8) * 128 + c) =
                        make_float2(acc[mt][nt][2] + bb0, acc[mt][nt][3] + bb1);
                    #pragma unroll
                    for (int e = 0; e < 4; ++e) acc[mt][nt][e] = 0.f;
                }
            }
        }
        BARG(barid);   // all reads of A0/A1 done before next tile writes
    }
}

// ---------------------------------------------------------------------------
extern "C" void kernel_launch(void* const* d_in, const int* in_sizes, int n_in,
                              void* d_out, int out_size) {
    const float* x          = (const float*)d_in[0];
    const float* edge_attr  = (const float*)d_in[1];
    const int*   edge_index = (const int*)d_in[2];   // int32
    const float* W1         = (const float*)d_in[3];
    const float* b1         = (const float*)d_in[4];
    const float* W2         = (const float*)d_in[5];
    const float* b2         = (const float*)d_in[6];
    float*       out        = (float*)d_out;

    const int* recv = edge_index + N_EDGES;

    cudaFuncSetAttribute(mma_mlp_kernel,
                         cudaFuncAttributeMaxDynamicSharedMemorySize, SMEM_SZ);

    prep_w_kernel<<<32, 256>>>(W1, W2);
    zero_hist_kernel<<<SCAN_BLKS, 1024>>>();
    hist_kernel<<<3125, 256>>>(recv);
    scan1_kernel<<<SCAN_BLKS, 1024>>>();
    scan2_kernel<<<1, 256>>>();
    scan3_kernel<<<SCAN_BLKS, 1024>>>();
    fill_kernel<<<3125, 256>>>(recv);
    gather_kernel<<<25000, 256>>>(edge_attr);
    mma_mlp_kernel<<<GRID_MLP, 512, SMEM_SZ>>>(x, b1, b2, out);
}